// round 1
// baseline (speedup 1.0000x reference)
#include <cuda_runtime.h>
#include <math_constants.h>

#define B_      4
#define N_      16384
#define STRIDE_ 4
#define K_      20
#define D_      64
#define DK_     67
#define KFS_    68
#define M_      4096
#define NQ_     (B_*M_)     // 16384
#define HID_    128
#define OUT_    128
#define TK_     128
#define SROW_   129

// scratch (no cudaMalloc allowed)
__device__ float g_kf[(size_t)B_*N_*KFS_];   // 17.8 MB, transformed features (padded rows)
__device__ float g_kn[B_*N_];                // key squared norms
__device__ int   g_nbr[NQ_*K_];              // global neighbor indices

// ---------------------------------------------------------------------------
// Kernel 1: per-point transform -> kf, norms, and passthrough outputs
// ---------------------------------------------------------------------------
__global__ void __launch_bounds__(256) k_prep(const float* __restrict__ x,
                                              const float* __restrict__ pos,
                                              const float* __restrict__ lfr,
                                              float* __restrict__ outp,
                                              int out_size)
{
    int n = blockIdx.x * blockDim.x + threadIdx.x;
    if (n >= B_*N_) return;
    const float* xr = x + (size_t)n * D_;
    const float* R  = lfr + (size_t)n * 9;
    float r[9];
#pragma unroll
    for (int i = 0; i < 9; i++) r[i] = R[i];

    float kf[DK_];
#pragma unroll
    for (int i = 0; i < 16; i++) kf[i] = xr[i];
    // kf vectors: v'_a = sum_b lf[b,a] * v_b   (R = lframes^T)
#pragma unroll
    for (int v = 0; v < 16; v++) {
        float b0 = xr[16+3*v+0], b1 = xr[16+3*v+1], b2 = xr[16+3*v+2];
#pragma unroll
        for (int a = 0; a < 3; a++)
            kf[16+3*v+a] = r[0*3+a]*b0 + r[1*3+a]*b1 + r[2*3+a]*b2;
    }
    float p0 = pos[n*3+0], p1 = pos[n*3+1], p2 = pos[n*3+2];
    kf[64] = p0; kf[65] = p1; kf[66] = p2;

    float s = 0.f;
#pragma unroll
    for (int i = 0; i < DK_; i++) { g_kf[(size_t)n*KFS_ + i] = kf[i]; s += kf[i]*kf[i]; }
    g_kf[(size_t)n*KFS_ + 67] = 0.f;
    g_kn[n] = s;

    // passthrough outputs for query points (n % STRIDE == 0)
    if ((n & 3) == 0) {
        int b   = n >> 14;                       // n / 16384
        int qid = b*M_ + ((n & (N_-1)) >> 2);
        const int off_pos = NQ_*OUT_;            // 2097152
        const int off_bat = off_pos + NQ_*3;     // 2146304
        const int off_lf  = off_bat + NQ_;       // 2162688
        if (out_size >= off_lf + NQ_*9) {
            float* pos_out = outp + off_pos;
            float* bat_out = outp + off_bat;
            float* lf_out  = outp + off_lf;
            pos_out[qid*3+0] = p0; pos_out[qid*3+1] = p1; pos_out[qid*3+2] = p2;
            bat_out[qid] = (float)b;
#pragma unroll
            for (int i = 0; i < 9; i++) lf_out[qid*9+i] = r[i];
        }
    }
}

// ---------------------------------------------------------------------------
// Warp-distributed top-K insert: lanes 0..19 hold the kept (dist,idx);
// th = current max of kept (uniform). All lanes call this (ballot inside).
// ---------------------------------------------------------------------------
__device__ __forceinline__ void topk_insert(float d2, int gidx,
                                            float& kd, int& ki, float& th, int lane)
{
    unsigned m = __ballot_sync(0xffffffffu, d2 < th);
    while (m) {
        int src = __ffs(m) - 1; m &= m - 1;
        float v  = __shfl_sync(0xffffffffu, d2,  src);
        int   vi = __shfl_sync(0xffffffffu, gidx, src);
        if (v < th) {
            // argmax over kept values (lanes >= 20 hold -inf, never chosen)
            float mx = kd; int ml = lane;
#pragma unroll
            for (int off = 16; off; off >>= 1) {
                float om = __shfl_xor_sync(0xffffffffu, mx, off);
                int   ol = __shfl_xor_sync(0xffffffffu, ml, off);
                if (om > mx || (om == mx && ol < ml)) { mx = om; ml = ol; }
            }
            if (lane == ml) { kd = v; ki = vi; }
            float t = kd;
#pragma unroll
            for (int off = 16; off; off >>= 1)
                t = fmaxf(t, __shfl_xor_sync(0xffffffffu, t, off));
            th = t;
        }
    }
}

// ---------------------------------------------------------------------------
// Kernel 2: exact KNN. Block = 256 threads = 8 warps, warp owns 2 queries.
// Key tiles of 128 staged in shared as [dim][key], row stride 129 (odd =>
// conflict-free STS and LDS). d2 = (qn + kn) - 2*dot.
// ---------------------------------------------------------------------------
__global__ void __launch_bounds__(256, 2) k_knn()
{
    __shared__ float skey[DK_ * SROW_];
    __shared__ float skn[TK_];
    __shared__ float sq[16 * KFS_];

    const int tid = threadIdx.x, lane = tid & 31, w = tid >> 5;
    const int qbase = blockIdx.x * 16;
    const int b = qbase >> 12;        // / 4096 (16 | 4096 -> same batch)
    const int kb0 = b * N_;

    for (int i = tid; i < 16*DK_; i += 256) {
        int qq = i / DK_, d = i - qq*DK_;
        int pt = kb0 + ((qbase + qq) - b*M_) * STRIDE_;
        sq[qq*KFS_ + d] = g_kf[(size_t)pt*KFS_ + d];
    }

    const int q0  = qbase + 2*w;
    const int pt0 = kb0 + (q0 - b*M_) * STRIDE_;
    const float qn0 = g_kn[pt0];
    const float qn1 = g_kn[pt0 + STRIDE_];
    const float* sq0 = &sq[(2*w)   * KFS_];
    const float* sq1 = &sq[(2*w+1) * KFS_];

    float kd0 = (lane < K_) ? CUDART_INF_F : -CUDART_INF_F; int ki0 = 0;
    float kd1 = kd0;                                        int ki1 = 0;
    float th0 = CUDART_INF_F, th1 = CUDART_INF_F;

    for (int tile = 0; tile < N_/TK_; tile++) {
        __syncthreads();
        // cooperative tile load: warp w loads keys [16w, 16w+16)
        {
            const int jb = w * 16;
#pragma unroll 4
            for (int kk = 0; kk < 16; kk++) {
                const float* row = g_kf + (size_t)(kb0 + tile*TK_ + jb + kk) * KFS_;
                skey[lane*SROW_        + jb + kk] = row[lane];
                skey[(lane+32)*SROW_   + jb + kk] = row[lane+32];
                if (lane < 3)
                    skey[(lane+64)*SROW_ + jb + kk] = row[lane+64];
            }
            if (tid < TK_) skn[tid] = g_kn[kb0 + tile*TK_ + tid];
        }
        __syncthreads();

        float a00=0.f,a01=0.f,a02=0.f,a03=0.f;
        float a10=0.f,a11=0.f,a12=0.f,a13=0.f;
#pragma unroll
        for (int d = 0; d < DK_; d++) {
            const float* kr = &skey[d * SROW_];
            float k0 = kr[lane], k1 = kr[lane+32], k2 = kr[lane+64], k3 = kr[lane+96];
            float v0 = sq0[d], v1 = sq1[d];
            a00 += v0*k0; a01 += v0*k1; a02 += v0*k2; a03 += v0*k3;
            a10 += v1*k0; a11 += v1*k1; a12 += v1*k2; a13 += v1*k3;
        }
        const float kn0 = skn[lane], kn1 = skn[lane+32], kn2 = skn[lane+64], kn3 = skn[lane+96];
        const int gi = kb0 + tile*TK_ + lane;
        float d2;
        d2 = (qn0+kn0) - 2.f*a00; topk_insert(d2, gi,    kd0, ki0, th0, lane);
        d2 = (qn0+kn1) - 2.f*a01; topk_insert(d2, gi+32, kd0, ki0, th0, lane);
        d2 = (qn0+kn2) - 2.f*a02; topk_insert(d2, gi+64, kd0, ki0, th0, lane);
        d2 = (qn0+kn3) - 2.f*a03; topk_insert(d2, gi+96, kd0, ki0, th0, lane);
        d2 = (qn1+kn0) - 2.f*a10; topk_insert(d2, gi,    kd1, ki1, th1, lane);
        d2 = (qn1+kn1) - 2.f*a11; topk_insert(d2, gi+32, kd1, ki1, th1, lane);
        d2 = (qn1+kn2) - 2.f*a12; topk_insert(d2, gi+64, kd1, ki1, th1, lane);
        d2 = (qn1+kn3) - 2.f*a13; topk_insert(d2, gi+96, kd1, ki1, th1, lane);
    }

    if (lane < K_) {
        g_nbr[q0*K_ + lane]     = ki0;
        g_nbr[(q0+1)*K_ + lane] = ki1;
    }
}

// ---------------------------------------------------------------------------
// Kernel 3: edge MLP + maxpool. Block = 8 warps, warp = 1 query,
// 5 groups x 4 edges; lane owns 4 output columns (float4 weight loads from L1).
// ---------------------------------------------------------------------------
__global__ void __launch_bounds__(256) k_mlp(const float* __restrict__ x,
                                             const float* __restrict__ lfr,
                                             const float* __restrict__ W1,
                                             const float* __restrict__ b1,
                                             const float* __restrict__ W2,
                                             const float* __restrict__ b2,
                                             float* __restrict__ outp)
{
    __shared__ float sxd[8][D_];
    __shared__ float slf[8][12];
    __shared__ float srel[8][4][D_];
    __shared__ float srl[8][4][D_];
    __shared__ __align__(16) float sa1[8][4][HID_];

    const int tid = threadIdx.x, lane = tid & 31, w = tid >> 5;
    const int q  = blockIdx.x * 8 + w;
    const int b  = q >> 12;
    const int pt = b*N_ + (q - b*M_) * STRIDE_;

    for (int d = lane; d < D_; d += 32) sxd[w][d] = x[(size_t)pt*D_ + d];
    if (lane < 9) slf[w][lane] = lfr[(size_t)pt*9 + lane];
    __syncwarp();

    const int c4 = lane * 4;
    float4 base = *(const float4*)(b1 + c4);
#pragma unroll 8
    for (int d = 0; d < D_; d++) {
        float xv = sxd[w][d];
        float4 w4 = __ldg((const float4*)(W1 + d*HID_ + c4));
        base.x += xv*w4.x; base.y += xv*w4.y; base.z += xv*w4.z; base.w += xv*w4.w;
    }
    const float4 b2v = __ldg((const float4*)(b2 + c4));
    float4 mx = make_float4(-CUDART_INF_F, -CUDART_INF_F, -CUDART_INF_F, -CUDART_INF_F);

    for (int grp = 0; grp < 5; grp++) {
        __syncwarp();
        int s = 0;
        if (lane < 4) s = g_nbr[q*K_ + grp*4 + lane];
        const int ss0 = __shfl_sync(0xffffffffu, s, 0);
        const int ss1 = __shfl_sync(0xffffffffu, s, 1);
        const int ss2 = __shfl_sync(0xffffffffu, s, 2);
        const int ss3 = __shfl_sync(0xffffffffu, s, 3);
        {
            const float* xs0 = x + (size_t)ss0 * D_;
            const float* xs1 = x + (size_t)ss1 * D_;
            const float* xs2 = x + (size_t)ss2 * D_;
            const float* xs3 = x + (size_t)ss3 * D_;
#pragma unroll
            for (int d = lane; d < D_; d += 32) {
                float xd = sxd[w][d];
                srel[w][0][d] = xs0[d] - xd;
                srel[w][1][d] = xs1[d] - xd;
                srel[w][2][d] = xs2[d] - xd;
                srel[w][3][d] = xs3[d] - xd;
            }
        }
        __syncwarp();
        // rotate rel -> rel_local with R = lf_dst (v'_a = sum_b lf[a,b] v_b)
#pragma unroll
        for (int t = 0; t < 8; t++) {
            int item = lane + 32*t;
            int e = item >> 6;
            int d = item & 63;
            float v;
            if (d < 16) v = srel[w][e][d];
            else {
                int dd = d - 16;
                int a  = dd % 3;
                int vb = 16 + dd - a;
                v = slf[w][a*3+0]*srel[w][e][vb]
                  + slf[w][a*3+1]*srel[w][e][vb+1]
                  + slf[w][a*3+2]*srel[w][e][vb+2];
            }
            srl[w][e][d] = v;
        }
        __syncwarp();

        float4 ac0 = {0,0,0,0}, ac1 = {0,0,0,0}, ac2 = {0,0,0,0}, ac3 = {0,0,0,0};
#pragma unroll 4
        for (int d = 0; d < D_; d++) {
            float4 w4 = __ldg((const float4*)(W1 + (D_+d)*HID_ + c4));
            float r0 = srl[w][0][d], r1 = srl[w][1][d], r2 = srl[w][2][d], r3 = srl[w][3][d];
            ac0.x += r0*w4.x; ac0.y += r0*w4.y; ac0.z += r0*w4.z; ac0.w += r0*w4.w;
            ac1.x += r1*w4.x; ac1.y += r1*w4.y; ac1.z += r1*w4.z; ac1.w += r1*w4.w;
            ac2.x += r2*w4.x; ac2.y += r2*w4.y; ac2.z += r2*w4.z; ac2.w += r2*w4.w;
            ac3.x += r3*w4.x; ac3.y += r3*w4.y; ac3.z += r3*w4.z; ac3.w += r3*w4.w;
        }
        {
            float4 a;
            a.x = fmaxf(base.x+ac0.x,0.f); a.y = fmaxf(base.y+ac0.y,0.f);
            a.z = fmaxf(base.z+ac0.z,0.f); a.w = fmaxf(base.w+ac0.w,0.f);
            *(float4*)&sa1[w][0][c4] = a;
            a.x = fmaxf(base.x+ac1.x,0.f); a.y = fmaxf(base.y+ac1.y,0.f);
            a.z = fmaxf(base.z+ac1.z,0.f); a.w = fmaxf(base.w+ac1.w,0.f);
            *(float4*)&sa1[w][1][c4] = a;
            a.x = fmaxf(base.x+ac2.x,0.f); a.y = fmaxf(base.y+ac2.y,0.f);
            a.z = fmaxf(base.z+ac2.z,0.f); a.w = fmaxf(base.w+ac2.w,0.f);
            *(float4*)&sa1[w][2][c4] = a;
            a.x = fmaxf(base.x+ac3.x,0.f); a.y = fmaxf(base.y+ac3.y,0.f);
            a.z = fmaxf(base.z+ac3.z,0.f); a.w = fmaxf(base.w+ac3.w,0.f);
            *(float4*)&sa1[w][3][c4] = a;
        }
        __syncwarp();

        float4 m0 = b2v, m1 = b2v, m2 = b2v, m3 = b2v;
#pragma unroll 4
        for (int j = 0; j < HID_; j++) {
            float4 w4 = __ldg((const float4*)(W2 + j*HID_ + c4));
            float a0 = sa1[w][0][j], a1 = sa1[w][1][j], a2 = sa1[w][2][j], a3 = sa1[w][3][j];
            m0.x += a0*w4.x; m0.y += a0*w4.y; m0.z += a0*w4.z; m0.w += a0*w4.w;
            m1.x += a1*w4.x; m1.y += a1*w4.y; m1.z += a1*w4.z; m1.w += a1*w4.w;
            m2.x += a2*w4.x; m2.y += a2*w4.y; m2.z += a2*w4.z; m2.w += a2*w4.w;
            m3.x += a3*w4.x; m3.y += a3*w4.y; m3.z += a3*w4.z; m3.w += a3*w4.w;
        }
        mx.x = fmaxf(fmaxf(fmaxf(fmaxf(mx.x, m0.x), m1.x), m2.x), m3.x);
        mx.y = fmaxf(fmaxf(fmaxf(fmaxf(mx.y, m0.y), m1.y), m2.y), m3.y);
        mx.z = fmaxf(fmaxf(fmaxf(fmaxf(mx.z, m0.z), m1.z), m2.z), m3.z);
        mx.w = fmaxf(fmaxf(fmaxf(fmaxf(mx.w, m0.w), m1.w), m2.w), m3.w);
    }

    *(float4*)(outp + (size_t)q*OUT_ + c4) = mx;
}

// ---------------------------------------------------------------------------
extern "C" void kernel_launch(void* const* d_in, const int* in_sizes, int n_in,
                              void* d_out, int out_size)
{
    const float* x   = (const float*)d_in[0];
    const float* pos = (const float*)d_in[1];
    const float* lfr = (const float*)d_in[2];
    /* d_in[3] = batch (int32), derived instead */
    const float* W1  = (const float*)d_in[4];
    const float* b1  = (const float*)d_in[5];
    const float* W2  = (const float*)d_in[6];
    const float* b2  = (const float*)d_in[7];
    float* outp = (float*)d_out;

    k_prep<<<(B_*N_ + 255)/256, 256>>>(x, pos, lfr, outp, out_size);
    k_knn<<<NQ_/16, 256>>>();
    k_mlp<<<NQ_/8, 256>>>(x, lfr, W1, b1, W2, b2, outp);
}

// round 2
// speedup vs baseline: 1.3630x; 1.3630x over previous
#include <cuda_runtime.h>
#include <math_constants.h>

#define B_      4
#define N_      16384
#define STRIDE_ 4
#define K_      20
#define D_      64
#define DK_     67
#define KFS_    68
#define M_      4096
#define NQ_     (B_*M_)     // 16384
#define HID_    128
#define OUT_    128
#define TK_     128         // keys per tile
#define QW_     8           // queries per warp
#define QB_     64          // queries per block

// scratch (no cudaMalloc allowed)
__device__ float g_kf[(size_t)B_*N_*KFS_];   // transformed features (padded rows, pad=0)
__device__ float g_kn[B_*N_];                // key squared norms
__device__ int   g_nbr[NQ_*K_];              // global neighbor indices

// ---------------------------------------------------------------------------
// Kernel 1: per-point transform -> kf, norms, and passthrough outputs
// ---------------------------------------------------------------------------
__global__ void __launch_bounds__(256) k_prep(const float* __restrict__ x,
                                              const float* __restrict__ pos,
                                              const float* __restrict__ lfr,
                                              float* __restrict__ outp,
                                              int out_size)
{
    int n = blockIdx.x * blockDim.x + threadIdx.x;
    if (n >= B_*N_) return;
    const float* xr = x + (size_t)n * D_;
    const float* R  = lfr + (size_t)n * 9;
    float r[9];
#pragma unroll
    for (int i = 0; i < 9; i++) r[i] = R[i];

    float kf[DK_];
#pragma unroll
    for (int i = 0; i < 16; i++) kf[i] = xr[i];
    // kf vectors: v'_a = sum_b lf[b,a] * v_b   (R = lframes^T)
#pragma unroll
    for (int v = 0; v < 16; v++) {
        float b0 = xr[16+3*v+0], b1 = xr[16+3*v+1], b2 = xr[16+3*v+2];
#pragma unroll
        for (int a = 0; a < 3; a++)
            kf[16+3*v+a] = r[0*3+a]*b0 + r[1*3+a]*b1 + r[2*3+a]*b2;
    }
    float p0 = pos[n*3+0], p1 = pos[n*3+1], p2 = pos[n*3+2];
    kf[64] = p0; kf[65] = p1; kf[66] = p2;

    float s = 0.f;
#pragma unroll
    for (int i = 0; i < DK_; i++) { g_kf[(size_t)n*KFS_ + i] = kf[i]; s += kf[i]*kf[i]; }
    g_kf[(size_t)n*KFS_ + 67] = 0.f;
    g_kn[n] = s;

    // passthrough outputs for query points (n % STRIDE == 0)
    if ((n & 3) == 0) {
        int b   = n >> 14;                       // n / 16384
        int qid = b*M_ + ((n & (N_-1)) >> 2);
        const int off_pos = NQ_*OUT_;            // 2097152
        const int off_bat = off_pos + NQ_*3;     // 2146304
        const int off_lf  = off_bat + NQ_;       // 2162688
        if (out_size >= off_lf + NQ_*9) {
            float* pos_out = outp + off_pos;
            float* bat_out = outp + off_bat;
            float* lf_out  = outp + off_lf;
            pos_out[qid*3+0] = p0; pos_out[qid*3+1] = p1; pos_out[qid*3+2] = p2;
            bat_out[qid] = (float)b;
#pragma unroll
            for (int i = 0; i < 9; i++) lf_out[qid*9+i] = r[i];
        }
    }
}

// ---------------------------------------------------------------------------
// Warp-distributed top-K insert: lanes 0..19 hold the kept (dist,idx);
// th = current max of kept (uniform). All lanes call this (ballot inside).
// ---------------------------------------------------------------------------
__device__ __forceinline__ void topk_insert(float d2, int gidx,
                                            float& kd, int& ki, float& th, int lane)
{
    unsigned m = __ballot_sync(0xffffffffu, d2 < th);
    while (m) {
        int src = __ffs(m) - 1; m &= m - 1;
        float v  = __shfl_sync(0xffffffffu, d2,  src);
        int   vi = __shfl_sync(0xffffffffu, gidx, src);
        if (v < th) {
            float mx = kd; int ml = lane;
#pragma unroll
            for (int off = 16; off; off >>= 1) {
                float om = __shfl_xor_sync(0xffffffffu, mx, off);
                int   ol = __shfl_xor_sync(0xffffffffu, ml, off);
                if (om > mx || (om == mx && ol < ml)) { mx = om; ml = ol; }
            }
            if (lane == ml) { kd = v; ki = vi; }
            float t = kd;
#pragma unroll
            for (int off = 16; off; off >>= 1)
                t = fmaxf(t, __shfl_xor_sync(0xffffffffu, t, off));
            th = t;
        }
    }
}

// ---------------------------------------------------------------------------
// Kernel 2: exact KNN, FMA-bound layout.
// Block = 256 threads = 8 warps; warp owns 8 queries; block owns 64 queries.
// Key tile [128][17 float4] in smem (row 272B, LDS.128 conflict-free);
// queries staged once [64][17 float4], read as broadcasts.
// d2' = kn - 2*dot (qn dropped; ordering invariant).
// ---------------------------------------------------------------------------
__global__ void __launch_bounds__(256, 2) k_knn()
{
    extern __shared__ float smem[];
    float4* skey4 = (float4*)smem;                 // [TK_][17]
    float*  skn   = smem + TK_*KFS_;               // [TK_]
    float4* sq4   = (float4*)(smem + TK_*KFS_ + TK_); // [QB_][17]

    const int tid = threadIdx.x, lane = tid & 31, w = tid >> 5;
    const int qbase = blockIdx.x * QB_;
    const int b = qbase >> 12;            // 64 | 4096 -> whole block same batch
    const int kb0 = b * N_;
    const float4* kf4 = (const float4*)g_kf;

    // stage this block's 64 query rows
    for (int i = tid; i < QB_*17; i += 256) {
        int qq = i / 17, g = i - qq*17;
        int pt = kb0 + ((qbase + qq) - b*M_) * STRIDE_;
        sq4[i] = kf4[(size_t)pt*17 + g];
    }

    float kd[QW_], th[QW_];
    int   ki[QW_];
#pragma unroll
    for (int q = 0; q < QW_; q++) {
        kd[q] = (lane < K_) ? CUDART_INF_F : -CUDART_INF_F;
        ki[q] = 0;
        th[q] = CUDART_INF_F;
    }
    const float4* sqw = sq4 + (w*QW_)*17;

    for (int tile = 0; tile < N_/TK_; tile++) {
        __syncthreads();
        {
            const float4* src = kf4 + (size_t)(kb0 + tile*TK_)*17;
            for (int i = tid; i < TK_*17; i += 256) skey4[i] = src[i];
            if (tid < TK_) skn[tid] = g_kn[kb0 + tile*TK_ + tid];
        }
        __syncthreads();

        float acc[QW_][4];
#pragma unroll
        for (int q = 0; q < QW_; q++) { acc[q][0]=0.f; acc[q][1]=0.f; acc[q][2]=0.f; acc[q][3]=0.f; }

#pragma unroll 1
        for (int g = 0; g < 17; g++) {
            float4 k0 = skey4[(lane     )*17 + g];
            float4 k1 = skey4[(lane + 32)*17 + g];
            float4 k2 = skey4[(lane + 64)*17 + g];
            float4 k3 = skey4[(lane + 96)*17 + g];
#pragma unroll
            for (int q = 0; q < QW_; q++) {
                float4 qv = sqw[q*17 + g];   // broadcast LDS.128
                acc[q][0] = fmaf(qv.x,k0.x, fmaf(qv.y,k0.y, fmaf(qv.z,k0.z, fmaf(qv.w,k0.w, acc[q][0]))));
                acc[q][1] = fmaf(qv.x,k1.x, fmaf(qv.y,k1.y, fmaf(qv.z,k1.z, fmaf(qv.w,k1.w, acc[q][1]))));
                acc[q][2] = fmaf(qv.x,k2.x, fmaf(qv.y,k2.y, fmaf(qv.z,k2.z, fmaf(qv.w,k2.w, acc[q][2]))));
                acc[q][3] = fmaf(qv.x,k3.x, fmaf(qv.y,k3.y, fmaf(qv.z,k3.z, fmaf(qv.w,k3.w, acc[q][3]))));
            }
        }

        const float kn0 = skn[lane], kn1 = skn[lane+32], kn2 = skn[lane+64], kn3 = skn[lane+96];
        const int gi = kb0 + tile*TK_ + lane;
#pragma unroll
        for (int q = 0; q < QW_; q++) {
            float d2;
            d2 = kn0 - 2.f*acc[q][0]; topk_insert(d2, gi,    kd[q], ki[q], th[q], lane);
            d2 = kn1 - 2.f*acc[q][1]; topk_insert(d2, gi+32, kd[q], ki[q], th[q], lane);
            d2 = kn2 - 2.f*acc[q][2]; topk_insert(d2, gi+64, kd[q], ki[q], th[q], lane);
            d2 = kn3 - 2.f*acc[q][3]; topk_insert(d2, gi+96, kd[q], ki[q], th[q], lane);
        }
    }

    if (lane < K_) {
#pragma unroll
        for (int q = 0; q < QW_; q++)
            g_nbr[(qbase + w*QW_ + q)*K_ + lane] = ki[q];
    }
}

// ---------------------------------------------------------------------------
// Kernel 3: edge MLP + maxpool. Block = 8 warps, warp = 1 query,
// 5 groups x 4 edges; lane owns 4 output columns (float4 weight loads from L1).
// ---------------------------------------------------------------------------
__global__ void __launch_bounds__(256) k_mlp(const float* __restrict__ x,
                                             const float* __restrict__ lfr,
                                             const float* __restrict__ W1,
                                             const float* __restrict__ b1,
                                             const float* __restrict__ W2,
                                             const float* __restrict__ b2,
                                             float* __restrict__ outp)
{
    __shared__ float sxd[8][D_];
    __shared__ float slf[8][12];
    __shared__ float srel[8][4][D_];
    __shared__ float srl[8][4][D_];
    __shared__ __align__(16) float sa1[8][4][HID_];

    const int tid = threadIdx.x, lane = tid & 31, w = tid >> 5;
    const int q  = blockIdx.x * 8 + w;
    const int b  = q >> 12;
    const int pt = b*N_ + (q - b*M_) * STRIDE_;

    for (int d = lane; d < D_; d += 32) sxd[w][d] = x[(size_t)pt*D_ + d];
    if (lane < 9) slf[w][lane] = lfr[(size_t)pt*9 + lane];
    __syncwarp();

    const int c4 = lane * 4;
    float4 base = *(const float4*)(b1 + c4);
#pragma unroll 8
    for (int d = 0; d < D_; d++) {
        float xv = sxd[w][d];
        float4 w4 = __ldg((const float4*)(W1 + d*HID_ + c4));
        base.x += xv*w4.x; base.y += xv*w4.y; base.z += xv*w4.z; base.w += xv*w4.w;
    }
    const float4 b2v = __ldg((const float4*)(b2 + c4));
    float4 mx = make_float4(-CUDART_INF_F, -CUDART_INF_F, -CUDART_INF_F, -CUDART_INF_F);

    for (int grp = 0; grp < 5; grp++) {
        __syncwarp();
        int s = 0;
        if (lane < 4) s = g_nbr[q*K_ + grp*4 + lane];
        const int ss0 = __shfl_sync(0xffffffffu, s, 0);
        const int ss1 = __shfl_sync(0xffffffffu, s, 1);
        const int ss2 = __shfl_sync(0xffffffffu, s, 2);
        const int ss3 = __shfl_sync(0xffffffffu, s, 3);
        {
            const float* xs0 = x + (size_t)ss0 * D_;
            const float* xs1 = x + (size_t)ss1 * D_;
            const float* xs2 = x + (size_t)ss2 * D_;
            const float* xs3 = x + (size_t)ss3 * D_;
#pragma unroll
            for (int d = lane; d < D_; d += 32) {
                float xd = sxd[w][d];
                srel[w][0][d] = xs0[d] - xd;
                srel[w][1][d] = xs1[d] - xd;
                srel[w][2][d] = xs2[d] - xd;
                srel[w][3][d] = xs3[d] - xd;
            }
        }
        __syncwarp();
        // rotate rel -> rel_local with R = lf_dst (v'_a = sum_b lf[a,b] v_b)
#pragma unroll
        for (int t = 0; t < 8; t++) {
            int item = lane + 32*t;
            int e = item >> 6;
            int d = item & 63;
            float v;
            if (d < 16) v = srel[w][e][d];
            else {
                int dd = d - 16;
                int a  = dd % 3;
                int vb = 16 + dd - a;
                v = slf[w][a*3+0]*srel[w][e][vb]
                  + slf[w][a*3+1]*srel[w][e][vb+1]
                  + slf[w][a*3+2]*srel[w][e][vb+2];
            }
            srl[w][e][d] = v;
        }
        __syncwarp();

        float4 ac0 = {0,0,0,0}, ac1 = {0,0,0,0}, ac2 = {0,0,0,0}, ac3 = {0,0,0,0};
#pragma unroll 4
        for (int d = 0; d < D_; d++) {
            float4 w4 = __ldg((const float4*)(W1 + (D_+d)*HID_ + c4));
            float r0 = srl[w][0][d], r1 = srl[w][1][d], r2 = srl[w][2][d], r3 = srl[w][3][d];
            ac0.x += r0*w4.x; ac0.y += r0*w4.y; ac0.z += r0*w4.z; ac0.w += r0*w4.w;
            ac1.x += r1*w4.x; ac1.y += r1*w4.y; ac1.z += r1*w4.z; ac1.w += r1*w4.w;
            ac2.x += r2*w4.x; ac2.y += r2*w4.y; ac2.z += r2*w4.z; ac2.w += r2*w4.w;
            ac3.x += r3*w4.x; ac3.y += r3*w4.y; ac3.z += r3*w4.z; ac3.w += r3*w4.w;
        }
        {
            float4 a;
            a.x = fmaxf(base.x+ac0.x,0.f); a.y = fmaxf(base.y+ac0.y,0.f);
            a.z = fmaxf(base.z+ac0.z,0.f); a.w = fmaxf(base.w+ac0.w,0.f);
            *(float4*)&sa1[w][0][c4] = a;
            a.x = fmaxf(base.x+ac1.x,0.f); a.y = fmaxf(base.y+ac1.y,0.f);
            a.z = fmaxf(base.z+ac1.z,0.f); a.w = fmaxf(base.w+ac1.w,0.f);
            *(float4*)&sa1[w][1][c4] = a;
            a.x = fmaxf(base.x+ac2.x,0.f); a.y = fmaxf(base.y+ac2.y,0.f);
            a.z = fmaxf(base.z+ac2.z,0.f); a.w = fmaxf(base.w+ac2.w,0.f);
            *(float4*)&sa1[w][2][c4] = a;
            a.x = fmaxf(base.x+ac3.x,0.f); a.y = fmaxf(base.y+ac3.y,0.f);
            a.z = fmaxf(base.z+ac3.z,0.f); a.w = fmaxf(base.w+ac3.w,0.f);
            *(float4*)&sa1[w][3][c4] = a;
        }
        __syncwarp();

        float4 m0 = b2v, m1 = b2v, m2 = b2v, m3 = b2v;
#pragma unroll 4
        for (int j = 0; j < HID_; j++) {
            float4 w4 = __ldg((const float4*)(W2 + j*HID_ + c4));
            float a0 = sa1[w][0][j], a1 = sa1[w][1][j], a2 = sa1[w][2][j], a3 = sa1[w][3][j];
            m0.x += a0*w4.x; m0.y += a0*w4.y; m0.z += a0*w4.z; m0.w += a0*w4.w;
            m1.x += a1*w4.x; m1.y += a1*w4.y; m1.z += a1*w4.z; m1.w += a1*w4.w;
            m2.x += a2*w4.x; m2.y += a2*w4.y; m2.z += a2*w4.z; m2.w += a2*w4.w;
            m3.x += a3*w4.x; m3.y += a3*w4.y; m3.z += a3*w4.z; m3.w += a3*w4.w;
        }
        mx.x = fmaxf(fmaxf(fmaxf(fmaxf(mx.x, m0.x), m1.x), m2.x), m3.x);
        mx.y = fmaxf(fmaxf(fmaxf(fmaxf(mx.y, m0.y), m1.y), m2.y), m3.y);
        mx.z = fmaxf(fmaxf(fmaxf(fmaxf(mx.z, m0.z), m1.z), m2.z), m3.z);
        mx.w = fmaxf(fmaxf(fmaxf(fmaxf(mx.w, m0.w), m1.w), m2.w), m3.w);
    }

    *(float4*)(outp + (size_t)q*OUT_ + c4) = mx;
}

// ---------------------------------------------------------------------------
extern "C" void kernel_launch(void* const* d_in, const int* in_sizes, int n_in,
                              void* d_out, int out_size)
{
    const float* x   = (const float*)d_in[0];
    const float* pos = (const float*)d_in[1];
    const float* lfr = (const float*)d_in[2];
    /* d_in[3] = batch (int32), derived instead */
    const float* W1  = (const float*)d_in[4];
    const float* b1  = (const float*)d_in[5];
    const float* W2  = (const float*)d_in[6];
    const float* b2  = (const float*)d_in[7];
    float* outp = (float*)d_out;

    const int knn_smem = (TK_*KFS_ + TK_ + QB_*KFS_) * (int)sizeof(float); // 52736 B
    static int s_attr_done = 0;
    // idempotent, host-side, capture-safe
    cudaFuncSetAttribute(k_knn, cudaFuncAttributeMaxDynamicSharedMemorySize, knn_smem);
    (void)s_attr_done;

    k_prep<<<(B_*N_ + 255)/256, 256>>>(x, pos, lfr, outp, out_size);
    k_knn<<<NQ_/QB_, 256, knn_smem>>>();
    k_mlp<<<NQ_/8, 256>>>(x, lfr, W1, b1, W2, b2, outp);
}